// round 13
// baseline (speedup 1.0000x reference)
#include <cuda_runtime.h>

#define NMAX  256
#define EDGES 2048
#define HDIM  64
#define EMBED 39
#define NT    1024
#define XS    68          // 272B rows: 16B-aligned float4 slots

#define FMA_F32X2(d, a, b, c) \
  asm("fma.rn.f32x2 %0, %1, %2, %3;" : "=l"(d) : "l"(a), "l"(b), "l"(c))
#define DUP_F32(d, f) \
  asm("mov.b64 %0, {%1, %1};" : "=l"(d) : "r"(__float_as_uint(f)))
#define BAR1_256() asm volatile("bar.sync 1, 256;" ::: "memory")

struct Smem {
  float xsA[NMAX * XS];            // features (persistent across layers)
  float xsB[NMAX * XS];            // h-tilde (transient per layer)
  float Ws[HDIM * HDIM];
  unsigned int epack[EDGES];       // src | dst<<8 | valid<<16
  unsigned int esorted[EDGES];     // valid edges by dst (src id only)
  unsigned long long skey64[NMAX];
  int   hist[NMAX];
  int   ofs[NMAX + 1];
  int   cursor[NMAX];
  float dinv[NMAX];
  int   newid[NMAX];
  int   oldidx[NMAX];
  float oscale[NMAX];
  __align__(16) float rsum[2 * HDIM];
  __align__(16) float bvec[HDIM];
  __align__(16) float pvec[HDIM];
  __align__(16) float h1[HDIM];
  float red[4];
};

__device__ __forceinline__ unsigned long long make_key(float s, int idx) {
  unsigned bits = __float_as_uint(s);
  unsigned m = (bits & 0x80000000u) ? ~bits : (bits | 0x80000000u);
  unsigned hi = ~m;
  return ((unsigned long long)hi << 32) | (unsigned)idx;
}
__device__ __forceinline__ float key_score(unsigned long long k) {
  unsigned m = ~(unsigned)(k >> 32);
  unsigned bits = (m & 0x80000000u) ? (m ^ 0x80000000u) : ~m;
  return __uint_as_float(bits);
}

__device__ __forceinline__ unsigned long long ce_shfl(unsigned long long k, int j, bool takeMin) {
  unsigned long long o = __shfl_xor_sync(0xffffffffu, k, j);
  unsigned long long mn = (o < k) ? o : k;
  unsigned long long mx = (o < k) ? k : o;
  return takeMin ? mn : mx;
}

__device__ __forceinline__ void smem_ce(unsigned long long* a, int tid, int j, int ksz) {
  if (tid < 128) {
    int low = tid & (j - 1);
    int i = ((tid ^ low) << 1) | low;
    int p = i | j;
    unsigned long long x = a[i], y = a[p];
    bool asc = ((i & ksz) == 0);
    bool sw = asc ? (x > y) : (x < y);
    if (sw) { a[i] = y; a[p] = x; }
  }
}

// ---- GEMM: thread = 4 rows (rg, rg+64, rg+128, rg+192) x 4 cols.
template <int K4, bool IND>
__device__ __forceinline__ void gemm(const float* __restrict__ cur,
                                     float* __restrict__ tmp,
                                     const float* __restrict__ Ws,
                                     const int* __restrict__ oldidx,
                                     const float* __restrict__ oscale,
                                     int n, int tid) {
  const int cg    = (tid & 7) | ((tid & 512) >> 6);
  const int rg    = (tid >> 3) & 63;
  const int cbase = cg * 4;
  int   src[4];
  float vs[4];
#pragma unroll
  for (int r = 0; r < 4; ++r) {
    const int row = rg + r * 64;
    if (IND) {
      if (row < n) { src[r] = oldidx[row]; vs[r] = oscale[row]; }
      else         { src[r] = row;         vs[r] = 0.f; }
    } else {
      src[r] = row;
    }
  }
  unsigned long long acc[4][2];
#pragma unroll
  for (int r = 0; r < 4; ++r) { acc[r][0] = 0ull; acc[r][1] = 0ull; }
#pragma unroll 4
  for (int k4 = 0; k4 < K4; ++k4) {
    float4 xv[4];
#pragma unroll
    for (int r = 0; r < 4; ++r)
      xv[r] = *reinterpret_cast<const float4*>(&cur[src[r] * XS + k4 * 4]);
#pragma unroll
    for (int kk = 0; kk < 4; ++kk) {
      const ulonglong2 w = *reinterpret_cast<const ulonglong2*>(&Ws[(k4 * 4 + kk) * HDIM + cbase]);
#pragma unroll
      for (int r = 0; r < 4; ++r) {
        unsigned long long xd;
        DUP_F32(xd, reinterpret_cast<const float*>(&xv[r])[kk]);
        FMA_F32X2(acc[r][0], xd, w.x, acc[r][0]);
        FMA_F32X2(acc[r][1], xd, w.y, acc[r][1]);
      }
    }
  }
#pragma unroll
  for (int r = 0; r < 4; ++r) {
    const int row = rg + r * 64;
    if (row < n) {
      if (IND) {
        unsigned long long vd;
        const unsigned long long z = 0ull;
        DUP_F32(vd, vs[r]);
        FMA_F32X2(acc[r][0], vd, acc[r][0], z);
        FMA_F32X2(acc[r][1], vd, acc[r][1], z);
      }
      *reinterpret_cast<unsigned long long*>(&tmp[row * XS + cbase])     = acc[r][0];
      *reinterpret_cast<unsigned long long*>(&tmp[row * XS + cbase + 2]) = acc[r][1];
    }
  }
}

__global__ __launch_bounds__(NT)
void gnn_kernel(const float* __restrict__ x,
                const int* __restrict__ ei,
                const float* __restrict__ W1, const float* __restrict__ b1, const float* __restrict__ p1,
                const float* __restrict__ W2, const float* __restrict__ b2, const float* __restrict__ p2,
                const float* __restrict__ W3, const float* __restrict__ b3, const float* __restrict__ p3,
                const float* __restrict__ lW1, const float* __restrict__ lb1,
                const float* __restrict__ lW2, const float* __restrict__ lb2,
                const float* __restrict__ lW3, const float* __restrict__ lb3,
                float* __restrict__ out) {
  extern __shared__ char smraw[];
  Smem& S = *reinterpret_cast<Smem*>(smraw);
  const int b    = blockIdx.x;
  const int tid  = threadIdx.x;
  const int lane = tid & 31;
  const int wid  = tid >> 5;
  const int hw   = tid >> 4;
  const int hl   = tid & 15;
  const unsigned hmask = 0xFFFFu << (tid & 16);

  // ---- clear hist, then pack edges + layer-0 histogram in one pass ----
  if (tid < NMAX) S.hist[tid] = 0;
  __syncthreads();
  const int* eb = ei + (size_t)b * 2 * EDGES;
  {
    const int2 s2 = *reinterpret_cast<const int2*>(&eb[tid * 2]);
    const int2 d2 = *reinterpret_cast<const int2*>(&eb[EDGES + tid * 2]);
    unsigned dx = (unsigned)d2.x & 255u, dy = (unsigned)d2.y & 255u;
    uint2 w;
    w.x = ((unsigned)s2.x & 255u) | (dx << 8) | (1u << 16);
    w.y = ((unsigned)s2.y & 255u) | (dy << 8) | (1u << 16);
    *reinterpret_cast<uint2*>(&S.epack[tid * 2]) = w;
    atomicAdd(&S.hist[dx], 1);
    atomicAdd(&S.hist[dy], 1);
  }
  // ---- stage x [256, 39] coalesced; zero col 39 ----
  const float* xb = x + (size_t)b * NMAX * EMBED;
  for (int idx = tid; idx < NMAX * EMBED; idx += NT) {
    int r = idx / EMBED, c = idx - r * EMBED;
    S.xsA[r * XS + c] = xb[idx];
  }
  if (tid < NMAX) S.xsA[tid * XS + EMBED] = 0.f;
  if (tid < 2 * HDIM) S.rsum[tid] = 0.f;

  float* const cur = S.xsA;
  float* const tmp = S.xsB;
  int n = NMAX;
  const int kk3[3] = {205, 164, 132};
  const float* Wl[3] = {W1, W2, W3};
  const float* bl[3] = {b1, b2, b3};
  const float* pl[3] = {p1, p2, p3};

  for (int layer = 0; layer < 3; ++layer) {
    // ---- stage weights / bias / p ----
    {
      const int nw = (layer == 0) ? EMBED * HDIM / 4 : HDIM * HDIM / 4;
      for (int idx = tid; idx < nw; idx += NT)
        reinterpret_cast<float4*>(S.Ws)[idx] = reinterpret_cast<const float4*>(Wl[layer])[idx];
      if (layer == 0 && tid >= 1008) {
        reinterpret_cast<float4*>(&S.Ws[EMBED * HDIM])[tid - 1008] = make_float4(0.f, 0.f, 0.f, 0.f);
      }
    }
    if (tid >= 64 && tid < 128) { int j = tid - 64; S.bvec[j] = bl[layer][j]; S.pvec[j] = pl[layer][j]; }
    if (wid == 30) {  // pscale = 1/||p||
      float a = pl[layer][lane], c2 = pl[layer][lane + 32];
      float s2 = a * a + c2 * c2;
#pragma unroll
      for (int o = 16; o; o >>= 1) s2 += __shfl_xor_sync(0xffffffffu, s2, o);
      if (lane == 0) S.red[0] = rsqrtf(s2);
    }
    __syncthreads();

    // ---- GEMM into tmp (indirect + score-scaled for layers 1,2) ----
    if (layer == 0) gemm<10, false>(cur, tmp, S.Ws, 0, 0, NMAX, tid);
    else            gemm<16, true >(cur, tmp, S.Ws, S.oldidx, S.oscale, n, tid);
    __syncthreads();

    // ---- single-warp scan over hist -> ofs / cursor / dinv; clears hist ----
    if (wid == 0) {
      int c[8];
#pragma unroll
      for (int q = 0; q < 8; ++q) { c[q] = S.hist[lane * 8 + q]; S.hist[lane * 8 + q] = 0; }
      int sum = 0;
#pragma unroll
      for (int q = 0; q < 8; ++q) sum += c[q];
      int incl = sum;
#pragma unroll
      for (int o = 1; o < 32; o <<= 1) {
        int t = __shfl_up_sync(0xffffffffu, incl, o);
        if (lane >= o) incl += t;
      }
      int run = incl - sum;
#pragma unroll
      for (int q = 0; q < 8; ++q) {
        int node = lane * 8 + q;
        S.ofs[node]    = run;
        S.cursor[node] = run;
        S.dinv[node]   = rsqrtf(1.0f + (float)c[q]);
        run += c[q];
      }
      if (lane == 31) S.ofs[NMAX] = run;
    }
    __syncthreads();

    // ---- scatter valid edges (src only), sorted by dst ----
#pragma unroll
    for (int e = tid; e < EDGES; e += NT) {
      unsigned u = S.epack[e];
      if (u >> 16) {
        int d = (u >> 8) & 255;
        int pos = atomicAdd(&S.cursor[d], 1);
        S.esorted[pos] = u & 255u;
      }
    }
    __syncthreads();

    // ---- aggregation (half-warp per node) + relu + fused score -> cur ----
    const float pscale = S.red[0];
    for (int i = hw; i < n; i += NT / 16) {
      const int beg = S.ofs[i], end = S.ofs[i + 1];
      const float di = S.dinv[i];
      unsigned long long a01 = 0ull, a23 = 0ull;
      for (int p = beg; p < end; ++p) {
        const int sN = S.esorted[p];
        unsigned long long cp;
        DUP_F32(cp, S.dinv[sN]);
        const ulonglong2 hv = *reinterpret_cast<const ulonglong2*>(&tmp[sN * XS + hl * 4]);
        FMA_F32X2(a01, cp, hv.x, a01);
        FMA_F32X2(a23, cp, hv.y, a23);
      }
      float av[4];
      asm("mov.b64 {%0, %1}, %2;" : "=f"(av[0]), "=f"(av[1]) : "l"(a01));
      asm("mov.b64 {%0, %1}, %2;" : "=f"(av[2]), "=f"(av[3]) : "l"(a23));
      const float4 hs = *reinterpret_cast<const float4*>(&tmp[i * XS + hl * 4]);
      const float4 bv = *reinterpret_cast<const float4*>(&S.bvec[hl * 4]);
      const float4 pv = *reinterpret_cast<const float4*>(&S.pvec[hl * 4]);
      const float idg = di * di;
      float v0 = fmaxf(av[0] * di + hs.x * idg + bv.x, 0.f);
      float v1 = fmaxf(av[1] * di + hs.y * idg + bv.y, 0.f);
      float v2 = fmaxf(av[2] * di + hs.z * idg + bv.z, 0.f);
      float v3 = fmaxf(av[3] * di + hs.w * idg + bv.w, 0.f);
      float4 vv = {v0, v1, v2, v3};
      *reinterpret_cast<float4*>(&cur[i * XS + hl * 4]) = vv;
      float sc = v0 * pv.x + v1 * pv.y + v2 * pv.z + v3 * pv.w;
#pragma unroll
      for (int o = 8; o; o >>= 1) sc += __shfl_xor_sync(hmask, sc, o);
      if (hl == 0) S.skey64[i] = make_key(tanhf(sc * pscale), i);
    }
    for (int i = n + tid; i < NMAX; i += NT) S.skey64[i] = make_key(-1e30f, i);
    if (tid < NMAX) S.newid[tid] = -1;
    __syncthreads();

    const int kcur = kk3[layer];
    // ---- bitonic sort 256 u64 keys; warps 0-7 only, named barrier ----
    if (tid < 256) {
      {
        unsigned long long k = S.skey64[tid];
#pragma unroll
        for (int ksz = 2; ksz <= 32; ksz <<= 1)
#pragma unroll
          for (int j = ksz >> 1; j > 0; j >>= 1)
            k = ce_shfl(k, j, ((tid & j) == 0) == ((tid & ksz) == 0));
        S.skey64[tid] = k;
      }
      BAR1_256();
#pragma unroll
      for (int ksz = 64; ksz <= 256; ksz <<= 1) {
        for (int j = ksz >> 1; j >= 32; j >>= 1) {
          smem_ce(S.skey64, tid, j, ksz);
          BAR1_256();
        }
        {
          unsigned long long k = S.skey64[tid];
          const bool asc = ((tid & ksz) == 0);
#pragma unroll
          for (int j = 16; j > 0; j >>= 1)
            k = ce_shfl(k, j, ((tid & j) == 0) == asc);
          S.skey64[tid] = k;
        }
        BAR1_256();
      }
      if (tid < kcur) {
        const unsigned long long key = S.skey64[tid];
        const int old = (int)(key & 0xffffffffull);
        S.newid[old]   = tid;
        S.oldidx[tid]  = old;
        S.oscale[tid]  = key_score(key);
      }
    }
    __syncthreads();

    // ---- fused: edge remap + next-layer histogram ----
    if (layer < 2) {
#pragma unroll
      for (int e = tid; e < EDGES; e += NT) {
        unsigned u = S.epack[e];
        int sN = u & 255, d = (u >> 8) & 255;
        int valid = (int)(u >> 16);
        int ns = S.newid[sN], nd = S.newid[d];
        int nv = (valid && ns >= 0 && nd >= 0) ? 1 : 0;
        if (ns < 0) ns = 0;
        if (nd < 0) nd = 0;
        S.epack[e] = (unsigned)ns | ((unsigned)nd << 8) | ((unsigned)nv << 16);
        if (nv) atomicAdd(&S.hist[nd], 1);
      }
    }
    // ---- readout: lane caches its (oldidx*XS, oscale) pairs ONCE, reuses per column ----
    {
      int   roff[7];
      float rsc[7];
#pragma unroll
      for (int j = 0; j < 7; ++j) {
        const int r = lane + 32 * j;
        if (r < kcur) { roff[j] = S.oldidx[r] * XS; rsc[j] = S.oscale[r]; }
        else          { roff[j] = 0;                rsc[j] = 0.f; }
      }
      for (int c = wid; c < HDIM; c += NT / 32) {
        float m = -1e30f, sm = 0.f;
#pragma unroll
        for (int j = 0; j < 7; ++j) {
          if (lane + 32 * j < kcur) {
            const float v = cur[roff[j] + c] * rsc[j];
            m = fmaxf(m, v);
            sm += v;
          }
        }
#pragma unroll
        for (int o = 16; o; o >>= 1) {
          m  = fmaxf(m, __shfl_xor_sync(0xffffffffu, m, o));
          sm += __shfl_xor_sync(0xffffffffu, sm, o);
        }
        if (lane == 0) {
          S.rsum[c]        += m;
          S.rsum[HDIM + c] += sm / (float)kcur;
        }
      }
    }
    n = kcur;
    __syncthreads();
  }

  // ---- MLP head: 128 -> 64 (256 threads) -> 32 -> 1 ----
  if (tid < 256) {
    int j = tid >> 2, q = tid & 3;
    float a = 0.f;
#pragma unroll 8
    for (int i = q * 32; i < q * 32 + 32; ++i) a += S.rsum[i] * lW1[i * 64 + j];
    a += __shfl_xor_sync(0xffffffffu, a, 1);
    a += __shfl_xor_sync(0xffffffffu, a, 2);
    if (q == 0) S.h1[j] = fmaxf(a + lb1[j], 0.f);
  }
  __syncthreads();
  if (tid < 32) {
    float a = lb2[tid];
#pragma unroll 8
    for (int j = 0; j < 64; ++j) a += S.h1[j] * lW2[j * 32 + tid];
    float h2 = fmaxf(a, 0.f);
    float v = h2 * lW3[tid];
#pragma unroll
    for (int o = 16; o; o >>= 1) v += __shfl_xor_sync(0xffffffffu, v, o);
    if (tid == 0) out[b] = 1.0f / (1.0f + expf(-(v + lb3[0])));
  }
}

extern "C" void kernel_launch(void* const* d_in, const int* in_sizes, int n_in,
                              void* d_out, int out_size) {
  const float* x   = (const float*)d_in[0];
  const int*   ei  = (const int*)d_in[1];
  const float* W1  = (const float*)d_in[2];
  const float* b1  = (const float*)d_in[3];
  const float* p1  = (const float*)d_in[4];
  const float* W2  = (const float*)d_in[5];
  const float* b2  = (const float*)d_in[6];
  const float* p2  = (const float*)d_in[7];
  const float* W3  = (const float*)d_in[8];
  const float* b3  = (const float*)d_in[9];
  const float* p3  = (const float*)d_in[10];
  const float* lW1 = (const float*)d_in[11];
  const float* lb1 = (const float*)d_in[12];
  const float* lW2 = (const float*)d_in[13];
  const float* lb2 = (const float*)d_in[14];
  const float* lW3 = (const float*)d_in[15];
  const float* lb3 = (const float*)d_in[16];
  float* out = (float*)d_out;

  const int B = in_sizes[0] / (NMAX * EMBED);
  const size_t sm = sizeof(Smem);
  cudaFuncSetAttribute(gnn_kernel, cudaFuncAttributeMaxDynamicSharedMemorySize, (int)sm);
  gnn_kernel<<<B, NT, sm>>>(x, ei, W1, b1, p1, W2, b2, p2, W3, b3, p3,
                            lW1, lb1, lW2, lb2, lW3, lb3, out);
}

// round 14
// speedup vs baseline: 1.7193x; 1.7193x over previous
#include <cuda_runtime.h>

#define NMAX  256
#define EDGES 2048
#define HDIM  64
#define EMBED 39
#define NT    1024
#define XS    68          // 272B rows: 16B-aligned float4 slots, plain layout

#define FMA_F32X2(d, a, b, c) \
  asm("fma.rn.f32x2 %0, %1, %2, %3;" : "=l"(d) : "l"(a), "l"(b), "l"(c))
#define DUP_F32(d, f) \
  asm("mov.b64 %0, {%1, %1};" : "=l"(d) : "r"(__float_as_uint(f)))
#define BAR1_256() asm volatile("bar.sync 1, 256;" ::: "memory")

struct Smem {
  float xsA[NMAX * XS];            // ping
  float xsB[NMAX * XS];            // pong
  float Ws[HDIM * HDIM];
  unsigned int epack[EDGES];       // src | dst<<8 | valid<<16
  unsigned int esorted[EDGES];     // valid edges by dst (src id only)
  unsigned long long skey64[NMAX];
  int   hist[NMAX];
  int   ofs[NMAX + 1];
  int   cursor[NMAX];
  float dinv[NMAX];
  int   newid[NMAX];
  __align__(16) float rsum[2 * HDIM];
  __align__(16) float bvec[HDIM];
  __align__(16) float pvec[HDIM];
  __align__(16) float h1[HDIM];
  float red[4];
};

__device__ __forceinline__ unsigned long long make_key(float s, int idx) {
  unsigned bits = __float_as_uint(s);
  unsigned m = (bits & 0x80000000u) ? ~bits : (bits | 0x80000000u);
  unsigned hi = ~m;
  return ((unsigned long long)hi << 32) | (unsigned)idx;
}
__device__ __forceinline__ float key_score(unsigned long long k) {
  unsigned m = ~(unsigned)(k >> 32);
  unsigned bits = (m & 0x80000000u) ? (m ^ 0x80000000u) : ~m;
  return __uint_as_float(bits);
}

__device__ __forceinline__ unsigned long long ce_shfl(unsigned long long k, int j, bool takeMin) {
  unsigned long long o = __shfl_xor_sync(0xffffffffu, k, j);
  unsigned long long mn = (o < k) ? o : k;
  unsigned long long mx = (o < k) ? k : o;
  return takeMin ? mn : mx;
}

__device__ __forceinline__ void smem_ce(unsigned long long* a, int tid, int j, int ksz) {
  if (tid < 128) {
    int low = tid & (j - 1);
    int i = ((tid ^ low) << 1) | low;
    int p = i | j;
    unsigned long long x = a[i], y = a[p];
    bool asc = ((i & ksz) == 0);
    bool sw = asc ? (x > y) : (x < y);
    if (sw) { a[i] = y; a[p] = x; }
  }
}

// ---- GEMM: 4 contiguous rows x 4 cols per thread (R11 layout) ----
__device__ __forceinline__ void gemm_epilogue(float* __restrict__ tmp, int row0, int n,
                                              int cbase, unsigned long long acc[4][2]) {
#pragma unroll
  for (int r = 0; r < 4; ++r) {
    const int row = row0 + r;
    if (row < n) {
      *reinterpret_cast<unsigned long long*>(&tmp[row * XS + cbase])     = acc[r][0];
      *reinterpret_cast<unsigned long long*>(&tmp[row * XS + cbase + 2]) = acc[r][1];
    }
  }
}

// layer 0 (K=39, plain input)
__device__ __forceinline__ void gemm_first(const float* __restrict__ cur,
                                           float* __restrict__ tmp,
                                           const float* __restrict__ Ws, int tid) {
  const int cbase = (tid & 15) * 4;
  const int row0  = (tid >> 4) * 4;
  unsigned long long acc[4][2];
#pragma unroll
  for (int r = 0; r < 4; ++r) { acc[r][0] = 0ull; acc[r][1] = 0ull; }
#pragma unroll 3
  for (int k = 0; k < EMBED; ++k) {
    const ulonglong2 w = *reinterpret_cast<const ulonglong2*>(&Ws[k * HDIM + cbase]);
#pragma unroll
    for (int r = 0; r < 4; ++r) {
      unsigned long long xa;
      DUP_F32(xa, cur[(row0 + r) * XS + k]);
      FMA_F32X2(acc[r][0], xa, w.x, acc[r][0]);
      FMA_F32X2(acc[r][1], xa, w.y, acc[r][1]);
    }
  }
  gemm_epilogue(tmp, row0, NMAX, cbase, acc);
}

// layers 1,2 (K=64, plain input, k-paired)
__device__ __forceinline__ void gemm_h(const float* __restrict__ cur,
                                       float* __restrict__ tmp,
                                       const float* __restrict__ Ws, int n, int tid) {
  const int cbase = (tid & 15) * 4;
  const int row0  = (tid >> 4) * 4;
  if (row0 >= n) return;
  unsigned long long acc[4][2];
#pragma unroll
  for (int r = 0; r < 4; ++r) { acc[r][0] = 0ull; acc[r][1] = 0ull; }
#pragma unroll 8
  for (int k2 = 0; k2 < 32; ++k2) {
    const ulonglong2 w0 = *reinterpret_cast<const ulonglong2*>(&Ws[(2 * k2)     * HDIM + cbase]);
    const ulonglong2 w1 = *reinterpret_cast<const ulonglong2*>(&Ws[(2 * k2 + 1) * HDIM + cbase]);
#pragma unroll
    for (int r = 0; r < 4; ++r) {
      const float2 xv = *reinterpret_cast<const float2*>(&cur[(row0 + r) * XS + 2 * k2]);
      unsigned long long xa, xb;
      DUP_F32(xa, xv.x);
      DUP_F32(xb, xv.y);
      FMA_F32X2(acc[r][0], xa, w0.x, acc[r][0]);
      FMA_F32X2(acc[r][1], xa, w0.y, acc[r][1]);
      FMA_F32X2(acc[r][0], xb, w1.x, acc[r][0]);
      FMA_F32X2(acc[r][1], xb, w1.y, acc[r][1]);
    }
  }
  gemm_epilogue(tmp, row0, n, cbase, acc);
}

__global__ __launch_bounds__(NT)
void gnn_kernel(const float* __restrict__ x,
                const int* __restrict__ ei,
                const float* __restrict__ W1, const float* __restrict__ b1, const float* __restrict__ p1,
                const float* __restrict__ W2, const float* __restrict__ b2, const float* __restrict__ p2,
                const float* __restrict__ W3, const float* __restrict__ b3, const float* __restrict__ p3,
                const float* __restrict__ lW1, const float* __restrict__ lb1,
                const float* __restrict__ lW2, const float* __restrict__ lb2,
                const float* __restrict__ lW3, const float* __restrict__ lb3,
                float* __restrict__ out) {
  extern __shared__ char smraw[];
  Smem& S = *reinterpret_cast<Smem*>(smraw);
  const int b    = blockIdx.x;
  const int tid  = threadIdx.x;
  const int lane = tid & 31;
  const int wid  = tid >> 5;
  const int hw   = tid >> 4;
  const int hl   = tid & 15;
  const unsigned hmask = 0xFFFFu << (tid & 16);

  // ---- clear hist, then pack edges + layer-0 histogram in one pass ----
  if (tid < NMAX) S.hist[tid] = 0;
  __syncthreads();
  const int* eb = ei + (size_t)b * 2 * EDGES;
  {
    const int2 s2 = *reinterpret_cast<const int2*>(&eb[tid * 2]);
    const int2 d2 = *reinterpret_cast<const int2*>(&eb[EDGES + tid * 2]);
    unsigned dx = (unsigned)d2.x & 255u, dy = (unsigned)d2.y & 255u;
    uint2 w;
    w.x = ((unsigned)s2.x & 255u) | (dx << 8) | (1u << 16);
    w.y = ((unsigned)s2.y & 255u) | (dy << 8) | (1u << 16);
    *reinterpret_cast<uint2*>(&S.epack[tid * 2]) = w;
    atomicAdd(&S.hist[dx], 1);
    atomicAdd(&S.hist[dy], 1);
  }
  // ---- stage x [256, 39] coalesced ----
  const float* xb = x + (size_t)b * NMAX * EMBED;
  for (int idx = tid; idx < NMAX * EMBED; idx += NT) {
    int r = idx / EMBED, c = idx - r * EMBED;
    S.xsA[r * XS + c] = xb[idx];
  }
  if (tid < 2 * HDIM) S.rsum[tid] = 0.f;

  float* cur = S.xsA;
  float* tmp = S.xsB;
  int n = NMAX;
  const int kk3[3] = {205, 164, 132};
  const float* Wl[3] = {W1, W2, W3};
  const float* bl[3] = {b1, b2, b3};
  const float* pl[3] = {p1, p2, p3};

  for (int layer = 0; layer < 3; ++layer) {
    const int KD = (layer == 0) ? EMBED : HDIM;
    // ---- stage weights / bias / p ----
    for (int idx = tid; idx < (KD * HDIM) / 4; idx += NT)
      reinterpret_cast<float4*>(S.Ws)[idx] = reinterpret_cast<const float4*>(Wl[layer])[idx];
    if (tid >= 64 && tid < 128) { int j = tid - 64; S.bvec[j] = bl[layer][j]; S.pvec[j] = pl[layer][j]; }
    if (wid == 30) {  // pscale = 1/||p||
      float a = pl[layer][lane], c2 = pl[layer][lane + 32];
      float s2 = a * a + c2 * c2;
#pragma unroll
      for (int o = 16; o; o >>= 1) s2 += __shfl_xor_sync(0xffffffffu, s2, o);
      if (lane == 0) S.red[0] = rsqrtf(s2);
    }
    __syncthreads();

    // ---- GEMM into tmp ----
    if (layer == 0) gemm_first(cur, tmp, S.Ws, tid);
    else            gemm_h(cur, tmp, S.Ws, n, tid);
    __syncthreads();

    // ---- single-warp scan over hist -> ofs / cursor / dinv; clears hist ----
    if (wid == 0) {
      int c[8];
#pragma unroll
      for (int q = 0; q < 8; ++q) { c[q] = S.hist[lane * 8 + q]; S.hist[lane * 8 + q] = 0; }
      int sum = 0;
#pragma unroll
      for (int q = 0; q < 8; ++q) sum += c[q];
      int incl = sum;
#pragma unroll
      for (int o = 1; o < 32; o <<= 1) {
        int t = __shfl_up_sync(0xffffffffu, incl, o);
        if (lane >= o) incl += t;
      }
      int run = incl - sum;
#pragma unroll
      for (int q = 0; q < 8; ++q) {
        int node = lane * 8 + q;
        S.ofs[node]    = run;
        S.cursor[node] = run;
        S.dinv[node]   = rsqrtf(1.0f + (float)c[q]);
        run += c[q];
      }
      if (lane == 31) S.ofs[NMAX] = run;
    }
    __syncthreads();

    // ---- scatter valid edges (src only), sorted by dst ----
#pragma unroll
    for (int e = tid; e < EDGES; e += NT) {
      unsigned u = S.epack[e];
      if (u >> 16) {
        int d = (u >> 8) & 255;
        int pos = atomicAdd(&S.cursor[d], 1);
        S.esorted[pos] = u & 255u;
      }
    }
    __syncthreads();

    // ---- aggregation (half-warp per node) + relu + fused score -> cur ----
    const float pscale = S.red[0];
    for (int i = hw; i < n; i += NT / 16) {
      const int beg = S.ofs[i], end = S.ofs[i + 1];
      const float di = S.dinv[i];
      unsigned long long a01 = 0ull, a23 = 0ull;
      for (int p = beg; p < end; ++p) {
        const int sN = S.esorted[p];
        unsigned long long cp;
        DUP_F32(cp, S.dinv[sN]);
        const ulonglong2 hv = *reinterpret_cast<const ulonglong2*>(&tmp[sN * XS + hl * 4]);
        FMA_F32X2(a01, cp, hv.x, a01);
        FMA_F32X2(a23, cp, hv.y, a23);
      }
      float av[4];
      asm("mov.b64 {%0, %1}, %2;" : "=f"(av[0]), "=f"(av[1]) : "l"(a01));
      asm("mov.b64 {%0, %1}, %2;" : "=f"(av[2]), "=f"(av[3]) : "l"(a23));
      const float4 hs = *reinterpret_cast<const float4*>(&tmp[i * XS + hl * 4]);
      const float4 bv = *reinterpret_cast<const float4*>(&S.bvec[hl * 4]);
      const float4 pv = *reinterpret_cast<const float4*>(&S.pvec[hl * 4]);
      const float idg = di * di;
      float v0 = fmaxf(av[0] * di + hs.x * idg + bv.x, 0.f);
      float v1 = fmaxf(av[1] * di + hs.y * idg + bv.y, 0.f);
      float v2 = fmaxf(av[2] * di + hs.z * idg + bv.z, 0.f);
      float v3 = fmaxf(av[3] * di + hs.w * idg + bv.w, 0.f);
      float4 vv = {v0, v1, v2, v3};
      *reinterpret_cast<float4*>(&cur[i * XS + hl * 4]) = vv;
      float sc = v0 * pv.x + v1 * pv.y + v2 * pv.z + v3 * pv.w;
#pragma unroll
      for (int o = 8; o; o >>= 1) sc += __shfl_xor_sync(hmask, sc, o);
      if (hl == 0) S.skey64[i] = make_key(tanhf(sc * pscale), i);
    }
    for (int i = n + tid; i < NMAX; i += NT) S.skey64[i] = make_key(-1e30f, i);
    if (tid < NMAX) S.newid[tid] = -1;
    __syncthreads();

    const int kcur = kk3[layer];
    // ---- bitonic sort 256 u64 keys; warps 0-7 only, named barrier ----
    if (tid < 256) {
      {
        unsigned long long k = S.skey64[tid];
#pragma unroll
        for (int ksz = 2; ksz <= 32; ksz <<= 1)
#pragma unroll
          for (int j = ksz >> 1; j > 0; j >>= 1)
            k = ce_shfl(k, j, ((tid & j) == 0) == ((tid & ksz) == 0));
        S.skey64[tid] = k;
      }
      BAR1_256();
#pragma unroll
      for (int ksz = 64; ksz <= 256; ksz <<= 1) {
        for (int j = ksz >> 1; j >= 32; j >>= 1) {
          smem_ce(S.skey64, tid, j, ksz);
          BAR1_256();
        }
        {
          unsigned long long k = S.skey64[tid];
          const bool asc = ((tid & ksz) == 0);
#pragma unroll
          for (int j = 16; j > 0; j >>= 1)
            k = ce_shfl(k, j, ((tid & j) == 0) == asc);
          S.skey64[tid] = k;
        }
        BAR1_256();
      }
      if (tid < kcur) {
        S.newid[(int)(S.skey64[tid] & 0xffffffffull)] = tid;
      }
    }
    __syncthreads();

    // ---- pooled rows -> tmp (scaled, half-warp per rank) ----
    for (int r = hw; r < kcur; r += NT / 16) {
      unsigned long long key = S.skey64[r];
      int old = (int)(key & 0xffffffffull);
      float v = key_score(key);
      float4 h4 = *reinterpret_cast<const float4*>(&cur[old * XS + hl * 4]);
      h4.x *= v; h4.y *= v; h4.z *= v; h4.w *= v;
      *reinterpret_cast<float4*>(&tmp[r * XS + hl * 4]) = h4;
    }
    // ---- fused: edge remap + next-layer histogram ----
    if (layer < 2) {
#pragma unroll
      for (int e = tid; e < EDGES; e += NT) {
        unsigned u = S.epack[e];
        int sN = u & 255, d = (u >> 8) & 255;
        int valid = (int)(u >> 16);
        int ns = S.newid[sN], nd = S.newid[d];
        int nv = (valid && ns >= 0 && nd >= 0) ? 1 : 0;
        if (ns < 0) ns = 0;
        if (nd < 0) nd = 0;
        S.epack[e] = (unsigned)ns | ((unsigned)nd << 8) | ((unsigned)nv << 16);
        if (nv) atomicAdd(&S.hist[nd], 1);
      }
    }
    __syncthreads();

    // ---- readout: warp per column (direct from tmp) ----
    for (int c = wid; c < HDIM; c += NT / 32) {
      float m = -1e30f, sm = 0.f;
      for (int r = lane; r < kcur; r += 32) {
        float v = tmp[r * XS + c];
        m = fmaxf(m, v);
        sm += v;
      }
#pragma unroll
      for (int o = 16; o; o >>= 1) {
        m  = fmaxf(m, __shfl_xor_sync(0xffffffffu, m, o));
        sm += __shfl_xor_sync(0xffffffffu, sm, o);
      }
      if (lane == 0) {
        S.rsum[c]        += m;
        S.rsum[HDIM + c] += sm / (float)kcur;
      }
    }
    float* t = cur; cur = tmp; tmp = t;
    n = kcur;
    __syncthreads();
  }

  // ---- MLP head: 128 -> 64 (256 threads) -> 32 -> 1 ----
  if (tid < 256) {
    int j = tid >> 2, q = tid & 3;
    float a = 0.f;
#pragma unroll 8
    for (int i = q * 32; i < q * 32 + 32; ++i) a += S.rsum[i] * lW1[i * 64 + j];
    a += __shfl_xor_sync(0xffffffffu, a, 1);
    a += __shfl_xor_sync(0xffffffffu, a, 2);
    if (q == 0) S.h1[j] = fmaxf(a + lb1[j], 0.f);
  }
  __syncthreads();
  if (tid < 32) {
    float a = lb2[tid];
#pragma unroll 8
    for (int j = 0; j < 64; ++j) a += S.h1[j] * lW2[j * 32 + tid];
    float h2 = fmaxf(a, 0.f);
    float v = h2 * lW3[tid];
#pragma unroll
    for (int o = 16; o; o >>= 1) v += __shfl_xor_sync(0xffffffffu, v, o);
    if (tid == 0) out[b] = 1.0f / (1.0f + expf(-(v + lb3[0])));
  }
}

extern "C" void kernel_launch(void* const* d_in, const int* in_sizes, int n_in,
                              void* d_out, int out_size) {
  const float* x   = (const float*)d_in[0];
  const int*   ei  = (const int*)d_in[1];
  const float* W1  = (const float*)d_in[2];
  const float* b1  = (const float*)d_in[3];
  const float* p1  = (const float*)d_in[4];
  const float* W2  = (const float*)d_in[5];
  const float* b2  = (const float*)d_in[6];
  const float* p2  = (const float*)d_in[7];
  const float* W3  = (const float*)d_in[8];
  const float* b3  = (const float*)d_in[9];
  const float* p3  = (const float*)d_in[10];
  const float* lW1 = (const float*)d_in[11];
  const float* lb1 = (const float*)d_in[12];
  const float* lW2 = (const float*)d_in[13];
  const float* lb2 = (const float*)d_in[14];
  const float* lW3 = (const float*)d_in[15];
  const float* lb3 = (const float*)d_in[16];
  float* out = (float*)d_out;

  const int B = in_sizes[0] / (NMAX * EMBED);
  const size_t sm = sizeof(Smem);
  cudaFuncSetAttribute(gnn_kernel, cudaFuncAttributeMaxDynamicSharedMemorySize, (int)sm);
  gnn_kernel<<<B, NT, sm>>>(x, ei, W1, b1, p1, W2, b2, p2, W3, b3, p3,
                            lW1, lb1, lW2, lb2, lW3, lb3, out);
}

// round 16
// speedup vs baseline: 1.7542x; 1.0203x over previous
#include <cuda_runtime.h>

#define NMAX  256
#define EDGES 2048
#define HDIM  64
#define EMBED 39
#define NT    1024
#define XS    68          // 272B rows: 16B-aligned float4 slots, plain layout

#define FMA_F32X2(d, a, b, c) \
  asm("fma.rn.f32x2 %0, %1, %2, %3;" : "=l"(d) : "l"(a), "l"(b), "l"(c))
#define DUP_F32(d, f) \
  asm("mov.b64 %0, {%1, %1};" : "=l"(d) : "r"(__float_as_uint(f)))
#define BAR1_256() asm volatile("bar.sync 1, 256;" ::: "memory")

struct Smem {
  float xsA[NMAX * XS];            // ping
  float xsB[NMAX * XS];            // pong
  float Ws[HDIM * HDIM];
  unsigned int epack[EDGES];       // src | dst<<8 | valid<<16
  unsigned int esorted[EDGES];     // valid edges by dst (src id only)
  unsigned long long skey64[NMAX];
  int   hist[NMAX];
  int   ofs[NMAX + 1];
  int   cursor[NMAX];
  float dinv[NMAX];
  int   newid[NMAX];
  __align__(16) float rsum[2 * HDIM];
  __align__(16) float bvec[HDIM];
  __align__(16) float pvec[HDIM];
  __align__(16) float h1[HDIM];
  float red[4];
};

__device__ __forceinline__ unsigned long long make_key(float s, int idx) {
  unsigned bits = __float_as_uint(s);
  unsigned m = (bits & 0x80000000u) ? ~bits : (bits | 0x80000000u);
  unsigned hi = ~m;
  return ((unsigned long long)hi << 32) | (unsigned)idx;
}
__device__ __forceinline__ float key_score(unsigned long long k) {
  unsigned m = ~(unsigned)(k >> 32);
  unsigned bits = (m & 0x80000000u) ? (m ^ 0x80000000u) : ~m;
  return __uint_as_float(bits);
}

__device__ __forceinline__ unsigned long long ce_shfl(unsigned long long k, int j, bool takeMin) {
  unsigned long long o = __shfl_xor_sync(0xffffffffu, k, j);
  unsigned long long mn = (o < k) ? o : k;
  unsigned long long mx = (o < k) ? k : o;
  return takeMin ? mn : mx;
}

__device__ __forceinline__ void smem_ce(unsigned long long* a, int tid, int j, int ksz) {
  if (tid < 128) {
    int low = tid & (j - 1);
    int i = ((tid ^ low) << 1) | low;
    int p = i | j;
    unsigned long long x = a[i], y = a[p];
    bool asc = ((i & ksz) == 0);
    bool sw = asc ? (x > y) : (x < y);
    if (sw) { a[i] = y; a[p] = x; }
  }
}

// ---- GEMM: 4 contiguous rows x 4 cols per thread; x loaded as float4 over k4 blocks.
// Lanes 0-15 share one row-group, 16-31 the next: 2 distinct x addrs per warp-instr.
template <int K4>
__device__ __forceinline__ void gemm(const float* __restrict__ cur,
                                     float* __restrict__ tmp,
                                     const float* __restrict__ Ws,
                                     int n, int tid) {
  const int cbase = (tid & 15) * 4;
  const int row0  = (tid >> 4) * 4;
  if (row0 >= n) return;
  unsigned long long acc[4][2];
#pragma unroll
  for (int r = 0; r < 4; ++r) { acc[r][0] = 0ull; acc[r][1] = 0ull; }
#pragma unroll 4
  for (int k4 = 0; k4 < K4; ++k4) {
    float4 xv[4];
#pragma unroll
    for (int r = 0; r < 4; ++r)
      xv[r] = *reinterpret_cast<const float4*>(&cur[(row0 + r) * XS + k4 * 4]);
#pragma unroll
    for (int kk = 0; kk < 4; ++kk) {
      const ulonglong2 w = *reinterpret_cast<const ulonglong2*>(&Ws[(k4 * 4 + kk) * HDIM + cbase]);
#pragma unroll
      for (int r = 0; r < 4; ++r) {
        unsigned long long xd;
        DUP_F32(xd, reinterpret_cast<const float*>(&xv[r])[kk]);
        FMA_F32X2(acc[r][0], xd, w.x, acc[r][0]);
        FMA_F32X2(acc[r][1], xd, w.y, acc[r][1]);
      }
    }
  }
#pragma unroll
  for (int r = 0; r < 4; ++r) {
    const int row = row0 + r;
    if (row < n) {
      *reinterpret_cast<unsigned long long*>(&tmp[row * XS + cbase])     = acc[r][0];
      *reinterpret_cast<unsigned long long*>(&tmp[row * XS + cbase + 2]) = acc[r][1];
    }
  }
}

__global__ __launch_bounds__(NT)
void gnn_kernel(const float* __restrict__ x,
                const int* __restrict__ ei,
                const float* __restrict__ W1, const float* __restrict__ b1, const float* __restrict__ p1,
                const float* __restrict__ W2, const float* __restrict__ b2, const float* __restrict__ p2,
                const float* __restrict__ W3, const float* __restrict__ b3, const float* __restrict__ p3,
                const float* __restrict__ lW1, const float* __restrict__ lb1,
                const float* __restrict__ lW2, const float* __restrict__ lb2,
                const float* __restrict__ lW3, const float* __restrict__ lb3,
                float* __restrict__ out) {
  extern __shared__ char smraw[];
  Smem& S = *reinterpret_cast<Smem*>(smraw);
  const int b    = blockIdx.x;
  const int tid  = threadIdx.x;
  const int lane = tid & 31;
  const int wid  = tid >> 5;
  const int hw   = tid >> 4;
  const int hl   = tid & 15;
  const unsigned hmask = 0xFFFFu << (tid & 16);

  // ---- clear hist, then pack edges + layer-0 histogram in one pass ----
  if (tid < NMAX) S.hist[tid] = 0;
  __syncthreads();
  const int* eb = ei + (size_t)b * 2 * EDGES;
  {
    const int2 s2 = *reinterpret_cast<const int2*>(&eb[tid * 2]);
    const int2 d2 = *reinterpret_cast<const int2*>(&eb[EDGES + tid * 2]);
    unsigned dx = (unsigned)d2.x & 255u, dy = (unsigned)d2.y & 255u;
    uint2 w;
    w.x = ((unsigned)s2.x & 255u) | (dx << 8) | (1u << 16);
    w.y = ((unsigned)s2.y & 255u) | (dy << 8) | (1u << 16);
    *reinterpret_cast<uint2*>(&S.epack[tid * 2]) = w;
    atomicAdd(&S.hist[dx], 1);
    atomicAdd(&S.hist[dy], 1);
  }
  // ---- stage x [256, 39] coalesced; zero col 39 (k4 padding) ----
  const float* xb = x + (size_t)b * NMAX * EMBED;
  for (int idx = tid; idx < NMAX * EMBED; idx += NT) {
    int r = idx / EMBED, c = idx - r * EMBED;
    S.xsA[r * XS + c] = xb[idx];
  }
  if (tid < NMAX) S.xsA[tid * XS + EMBED] = 0.f;
  if (tid < 2 * HDIM) S.rsum[tid] = 0.f;

  float* cur = S.xsA;
  float* tmp = S.xsB;
  int n = NMAX;
  const int kk3[3] = {205, 164, 132};
  const float* Wl[3] = {W1, W2, W3};
  const float* bl[3] = {b1, b2, b3};
  const float* pl[3] = {p1, p2, p3};

  for (int layer = 0; layer < 3; ++layer) {
    // ---- stage weights / bias / p ----
    {
      const int nw = (layer == 0) ? EMBED * HDIM / 4 : HDIM * HDIM / 4;
      for (int idx = tid; idx < nw; idx += NT)
        reinterpret_cast<float4*>(S.Ws)[idx] = reinterpret_cast<const float4*>(Wl[layer])[idx];
      if (layer == 0 && tid >= 1008) {  // zero Ws row 39 (k4 padding)
        reinterpret_cast<float4*>(&S.Ws[EMBED * HDIM])[tid - 1008] = make_float4(0.f, 0.f, 0.f, 0.f);
      }
    }
    if (tid >= 64 && tid < 128) { int j = tid - 64; S.bvec[j] = bl[layer][j]; S.pvec[j] = pl[layer][j]; }
    if (wid == 30) {  // pscale = 1/||p||
      float a = pl[layer][lane], c2 = pl[layer][lane + 32];
      float s2 = a * a + c2 * c2;
#pragma unroll
      for (int o = 16; o; o >>= 1) s2 += __shfl_xor_sync(0xffffffffu, s2, o);
      if (lane == 0) S.red[0] = rsqrtf(s2);
    }
    __syncthreads();

    // ---- GEMM into tmp ----
    if (layer == 0) gemm<10>(cur, tmp, S.Ws, NMAX, tid);
    else            gemm<16>(cur, tmp, S.Ws, n, tid);
    __syncthreads();

    // ---- single-warp scan over hist -> ofs / cursor / dinv; clears hist ----
    if (wid == 0) {
      int c[8];
#pragma unroll
      for (int q = 0; q < 8; ++q) { c[q] = S.hist[lane * 8 + q]; S.hist[lane * 8 + q] = 0; }
      int sum = 0;
#pragma unroll
      for (int q = 0; q < 8; ++q) sum += c[q];
      int incl = sum;
#pragma unroll
      for (int o = 1; o < 32; o <<= 1) {
        int t = __shfl_up_sync(0xffffffffu, incl, o);
        if (lane >= o) incl += t;
      }
      int run = incl - sum;
#pragma unroll
      for (int q = 0; q < 8; ++q) {
        int node = lane * 8 + q;
        S.ofs[node]    = run;
        S.cursor[node] = run;
        S.dinv[node]   = rsqrtf(1.0f + (float)c[q]);
        run += c[q];
      }
      if (lane == 31) S.ofs[NMAX] = run;
    }
    __syncthreads();

    // ---- scatter valid edges (src only), sorted by dst ----
#pragma unroll
    for (int e = tid; e < EDGES; e += NT) {
      unsigned u = S.epack[e];
      if (u >> 16) {
        int d = (u >> 8) & 255;
        int pos = atomicAdd(&S.cursor[d], 1);
        S.esorted[pos] = u & 255u;
      }
    }
    __syncthreads();

    // ---- aggregation (half-warp per node) + relu + fused score -> cur ----
    const float pscale = S.red[0];
    for (int i = hw; i < n; i += NT / 16) {
      const int beg = S.ofs[i], end = S.ofs[i + 1];
      const float di = S.dinv[i];
      unsigned long long a01 = 0ull, a23 = 0ull;
      for (int p = beg; p < end; ++p) {
        const int sN = S.esorted[p];
        unsigned long long cp;
        DUP_F32(cp, S.dinv[sN]);
        const ulonglong2 hv = *reinterpret_cast<const ulonglong2*>(&tmp[sN * XS + hl * 4]);
        FMA_F32X2(a01, cp, hv.x, a01);
        FMA_F32X2(a23, cp, hv.y, a23);
      }
      float av[4];
      asm("mov.b64 {%0, %1}, %2;" : "=f"(av[0]), "=f"(av[1]) : "l"(a01));
      asm("mov.b64 {%0, %1}, %2;" : "=f"(av[2]), "=f"(av[3]) : "l"(a23));
      const float4 hs = *reinterpret_cast<const float4*>(&tmp[i * XS + hl * 4]);
      const float4 bv = *reinterpret_cast<const float4*>(&S.bvec[hl * 4]);
      const float4 pv = *reinterpret_cast<const float4*>(&S.pvec[hl * 4]);
      const float idg = di * di;
      float v0 = fmaxf(av[0] * di + hs.x * idg + bv.x, 0.f);
      float v1 = fmaxf(av[1] * di + hs.y * idg + bv.y, 0.f);
      float v2 = fmaxf(av[2] * di + hs.z * idg + bv.z, 0.f);
      float v3 = fmaxf(av[3] * di + hs.w * idg + bv.w, 0.f);
      float4 vv = {v0, v1, v2, v3};
      *reinterpret_cast<float4*>(&cur[i * XS + hl * 4]) = vv;
      float sc = v0 * pv.x + v1 * pv.y + v2 * pv.z + v3 * pv.w;
#pragma unroll
      for (int o = 8; o; o >>= 1) sc += __shfl_xor_sync(hmask, sc, o);
      if (hl == 0) S.skey64[i] = make_key(tanhf(sc * pscale), i);
    }
    for (int i = n + tid; i < NMAX; i += NT) S.skey64[i] = make_key(-1e30f, i);
    if (tid < NMAX) S.newid[tid] = -1;
    __syncthreads();

    const int kcur = kk3[layer];
    // ---- bitonic sort 256 u64 keys; warps 0-7 only, named barrier ----
    if (tid < 256) {
      {
        unsigned long long k = S.skey64[tid];
#pragma unroll
        for (int ksz = 2; ksz <= 32; ksz <<= 1)
#pragma unroll
          for (int j = ksz >> 1; j > 0; j >>= 1)
            k = ce_shfl(k, j, ((tid & j) == 0) == ((tid & ksz) == 0));
        S.skey64[tid] = k;
      }
      BAR1_256();
#pragma unroll
      for (int ksz = 64; ksz <= 256; ksz <<= 1) {
        for (int j = ksz >> 1; j >= 32; j >>= 1) {
          smem_ce(S.skey64, tid, j, ksz);
          BAR1_256();
        }
        {
          unsigned long long k = S.skey64[tid];
          const bool asc = ((tid & ksz) == 0);
#pragma unroll
          for (int j = 16; j > 0; j >>= 1)
            k = ce_shfl(k, j, ((tid & j) == 0) == asc);
          S.skey64[tid] = k;
        }
        BAR1_256();
      }
      if (tid < kcur) {
        S.newid[(int)(S.skey64[tid] & 0xffffffffull)] = tid;
      }
    }
    __syncthreads();

    // ---- pooled rows -> tmp (scaled, half-warp per rank) ----
    for (int r = hw; r < kcur; r += NT / 16) {
      unsigned long long key = S.skey64[r];
      int old = (int)(key & 0xffffffffull);
      float v = key_score(key);
      float4 h4 = *reinterpret_cast<const float4*>(&cur[old * XS + hl * 4]);
      h4.x *= v; h4.y *= v; h4.z *= v; h4.w *= v;
      *reinterpret_cast<float4*>(&tmp[r * XS + hl * 4]) = h4;
    }
    // zero pooled pad col 39 for next layer's k4 blocks (features live in tmp now)
    if (layer == 0 && tid < NMAX) tmp[tid * XS + EMBED] = 0.f;
    // ---- fused: edge remap + next-layer histogram ----
    if (layer < 2) {
#pragma unroll
      for (int e = tid; e < EDGES; e += NT) {
        unsigned u = S.epack[e];
        int sN = u & 255, d = (u >> 8) & 255;
        int valid = (int)(u >> 16);
        int ns = S.newid[sN], nd = S.newid[d];
        int nv = (valid && ns >= 0 && nd >= 0) ? 1 : 0;
        if (ns < 0) ns = 0;
        if (nd < 0) nd = 0;
        S.epack[e] = (unsigned)ns | ((unsigned)nd << 8) | ((unsigned)nv << 16);
        if (nv) atomicAdd(&S.hist[nd], 1);
      }
    }
    __syncthreads();

    // ---- readout: warp per column (direct from tmp) ----
    for (int c = wid; c < HDIM; c += NT / 32) {
      float m = -1e30f, sm = 0.f;
      for (int r = lane; r < kcur; r += 32) {
        float v = tmp[r * XS + c];
        m = fmaxf(m, v);
        sm += v;
      }
#pragma unroll
      for (int o = 16; o; o >>= 1) {
        m  = fmaxf(m, __shfl_xor_sync(0xffffffffu, m, o));
        sm += __shfl_xor_sync(0xffffffffu, sm, o);
      }
      if (lane == 0) {
        S.rsum[c]        += m;
        S.rsum[HDIM + c] += sm / (float)kcur;
      }
    }
    float* t = cur; cur = tmp; tmp = t;
    n = kcur;
    __syncthreads();
  }

  // ---- MLP head: 128 -> 64 (256 threads) -> 32 -> 1 ----
  if (tid < 256) {
    int j = tid >> 2, q = tid & 3;
    float a = 0.f;
#pragma unroll 8
    for (int i = q * 32; i < q * 32 + 32; ++i) a += S.rsum[i] * lW1[i * 64 + j];
    a += __shfl_xor_sync(0xffffffffu, a, 1);
    a += __shfl_xor_sync(0xffffffffu, a, 2);
    if (q == 0) S.h1[j] = fmaxf(a + lb1[j], 0.f);
  }
  __syncthreads();
  if (tid < 32) {
    float a = lb2[tid];
#pragma unroll 8
    for (int j = 0; j < 64; ++j) a += S.h1[j] * lW2[j * 32 + tid];
    float h2 = fmaxf(a, 0.f);
    float v = h2 * lW3[tid];
#pragma unroll
    for (int o = 16; o; o >>= 1) v += __shfl_xor_sync(0xffffffffu, v, o);
    if (tid == 0) out[b] = 1.0f / (1.0f + expf(-(v + lb3[0])));
  }
}

extern "C" void kernel_launch(void* const* d_in, const int* in_sizes, int n_in,
                              void* d_out, int out_size) {
  const float* x   = (const float*)d_in[0];
  const int*   ei  = (const int*)d_in[1];
  const float* W1  = (const float*)d_in[2];
  const float* b1  = (const float*)d_in[3];
  const float* p1  = (const float*)d_in[4];
  const float* W2  = (const float*)d_in[5];
  const float* b2  = (const float*)d_in[6];
  const float* p2  = (const float*)d_in[7];
  const float* W3  = (const float*)d_in[8];
  const float* b3  = (const float*)d_in[9];
  const float* p3  = (const float*)d_in[10];
  const float* lW1 = (const float*)d_in[11];
  const float* lb1 = (const float*)d_in[12];
  const float* lW2 = (const float*)d_in[13];
  const float* lb2 = (const float*)d_in[14];
  const float* lW3 = (const float*)d_in[15];
  const float* lb3 = (const float*)d_in[16];
  float* out = (float*)d_out;

  const int B = in_sizes[0] / (NMAX * EMBED);
  const size_t sm = sizeof(Smem);
  cudaFuncSetAttribute(gnn_kernel, cudaFuncAttributeMaxDynamicSharedMemorySize, (int)sm);
  gnn_kernel<<<B, NT, sm>>>(x, ei, W1, b1, p1, W2, b2, p2, W3, b3, p3,
                            lW1, lb1, lW2, lb2, lW3, lb3, out);
}

// round 17
// speedup vs baseline: 1.7640x; 1.0055x over previous
#include <cuda_runtime.h>

#define NMAX  256
#define EDGES 2048
#define HDIM  64
#define EMBED 39
#define NT    1024
#define XS    68          // 272B rows: 16B-aligned float4 slots, plain layout

#define FMA_F32X2(d, a, b, c) \
  asm("fma.rn.f32x2 %0, %1, %2, %3;" : "=l"(d) : "l"(a), "l"(b), "l"(c))
#define DUP_F32(d, f) \
  asm("mov.b64 %0, {%1, %1};" : "=l"(d) : "r"(__float_as_uint(f)))
#define BAR1_256() asm volatile("bar.sync 1, 256;" ::: "memory")

struct Smem {
  float xsA[NMAX * XS];            // ping
  float xsB[NMAX * XS];            // pong
  float Ws[HDIM * HDIM];
  unsigned int epack[EDGES];       // src | dst<<8 | valid<<16
  unsigned int esorted[EDGES];     // valid edges by dst (src id only)
  unsigned long long skey64[NMAX];
  int   hist[NMAX];
  int   ofs[NMAX + 1];
  int   cursor[NMAX];
  float dinv[NMAX];
  int   newid[NMAX];
  __align__(16) float rsum[2 * HDIM];
  __align__(16) float bvec[HDIM];
  __align__(16) float pvec[HDIM];
  __align__(16) float h1[HDIM];
  float red[4];
};

__device__ __forceinline__ unsigned long long make_key(float s, int idx) {
  unsigned bits = __float_as_uint(s);
  unsigned m = (bits & 0x80000000u) ? ~bits : (bits | 0x80000000u);
  unsigned hi = ~m;
  return ((unsigned long long)hi << 32) | (unsigned)idx;
}
__device__ __forceinline__ float key_score(unsigned long long k) {
  unsigned m = ~(unsigned)(k >> 32);
  unsigned bits = (m & 0x80000000u) ? (m ^ 0x80000000u) : ~m;
  return __uint_as_float(bits);
}

__device__ __forceinline__ unsigned long long ce_shfl(unsigned long long k, int j, bool takeMin) {
  unsigned long long o = __shfl_xor_sync(0xffffffffu, k, j);
  unsigned long long mn = (o < k) ? o : k;
  unsigned long long mx = (o < k) ? k : o;
  return takeMin ? mn : mx;
}

__device__ __forceinline__ void smem_ce(unsigned long long* a, int tid, int j, int ksz) {
  if (tid < 128) {
    int low = tid & (j - 1);
    int i = ((tid ^ low) << 1) | low;
    int p = i | j;
    unsigned long long x = a[i], y = a[p];
    bool asc = ((i & ksz) == 0);
    bool sw = asc ? (x > y) : (x < y);
    if (sw) { a[i] = y; a[p] = x; }
  }
}

// ---- GEMM: 4 contiguous rows x 4 cols per thread; x loaded as float4 over k4 blocks.
template <int K4>
__device__ __forceinline__ void gemm(const float* __restrict__ cur,
                                     float* __restrict__ tmp,
                                     const float* __restrict__ Ws,
                                     int n, int tid) {
  const int cbase = (tid & 15) * 4;
  const int row0  = (tid >> 4) * 4;
  if (row0 >= n) return;
  unsigned long long acc[4][2];
#pragma unroll
  for (int r = 0; r < 4; ++r) { acc[r][0] = 0ull; acc[r][1] = 0ull; }
#pragma unroll 4
  for (int k4 = 0; k4 < K4; ++k4) {
    float4 xv[4];
#pragma unroll
    for (int r = 0; r < 4; ++r)
      xv[r] = *reinterpret_cast<const float4*>(&cur[(row0 + r) * XS + k4 * 4]);
#pragma unroll
    for (int kk = 0; kk < 4; ++kk) {
      const ulonglong2 w = *reinterpret_cast<const ulonglong2*>(&Ws[(k4 * 4 + kk) * HDIM + cbase]);
#pragma unroll
      for (int r = 0; r < 4; ++r) {
        unsigned long long xd;
        DUP_F32(xd, reinterpret_cast<const float*>(&xv[r])[kk]);
        FMA_F32X2(acc[r][0], xd, w.x, acc[r][0]);
        FMA_F32X2(acc[r][1], xd, w.y, acc[r][1]);
      }
    }
  }
#pragma unroll
  for (int r = 0; r < 4; ++r) {
    const int row = row0 + r;
    if (row < n) {
      *reinterpret_cast<unsigned long long*>(&tmp[row * XS + cbase])     = acc[r][0];
      *reinterpret_cast<unsigned long long*>(&tmp[row * XS + cbase + 2]) = acc[r][1];
    }
  }
}

__global__ __launch_bounds__(NT)
void gnn_kernel(const float* __restrict__ x,
                const int* __restrict__ ei,
                const float* __restrict__ W1, const float* __restrict__ b1, const float* __restrict__ p1,
                const float* __restrict__ W2, const float* __restrict__ b2, const float* __restrict__ p2,
                const float* __restrict__ W3, const float* __restrict__ b3, const float* __restrict__ p3,
                const float* __restrict__ lW1, const float* __restrict__ lb1,
                const float* __restrict__ lW2, const float* __restrict__ lb2,
                const float* __restrict__ lW3, const float* __restrict__ lb3,
                float* __restrict__ out) {
  extern __shared__ char smraw[];
  Smem& S = *reinterpret_cast<Smem*>(smraw);
  const int b    = blockIdx.x;
  const int tid  = threadIdx.x;
  const int lane = tid & 31;
  const int wid  = tid >> 5;
  const int hw   = tid >> 4;
  const int hl   = tid & 15;
  const unsigned hmask = 0xFFFFu << (tid & 16);

  // ---- clear hist, then pack edges + layer-0 histogram in one pass ----
  if (tid < NMAX) S.hist[tid] = 0;
  __syncthreads();
  const int* eb = ei + (size_t)b * 2 * EDGES;
  {
    const int2 s2 = *reinterpret_cast<const int2*>(&eb[tid * 2]);
    const int2 d2 = *reinterpret_cast<const int2*>(&eb[EDGES + tid * 2]);
    unsigned dx = (unsigned)d2.x & 255u, dy = (unsigned)d2.y & 255u;
    uint2 w;
    w.x = ((unsigned)s2.x & 255u) | (dx << 8) | (1u << 16);
    w.y = ((unsigned)s2.y & 255u) | (dy << 8) | (1u << 16);
    *reinterpret_cast<uint2*>(&S.epack[tid * 2]) = w;
    atomicAdd(&S.hist[dx], 1);
    atomicAdd(&S.hist[dy], 1);
  }
  // ---- stage x [256, 39] coalesced; zero col 39 (k4 padding, layer 0 only) ----
  const float* xb = x + (size_t)b * NMAX * EMBED;
  for (int idx = tid; idx < NMAX * EMBED; idx += NT) {
    int r = idx / EMBED, c = idx - r * EMBED;
    S.xsA[r * XS + c] = xb[idx];
  }
  if (tid < NMAX) S.xsA[tid * XS + EMBED] = 0.f;
  if (tid < 2 * HDIM) S.rsum[tid] = 0.f;

  float* cur = S.xsA;
  float* tmp = S.xsB;
  int n = NMAX;
  const int kk3[3] = {205, 164, 132};
  const float* Wl[3] = {W1, W2, W3};
  const float* bl[3] = {b1, b2, b3};
  const float* pl[3] = {p1, p2, p3};

  for (int layer = 0; layer < 3; ++layer) {
    // ---- stage weights / bias / p ----
    {
      const int nw = (layer == 0) ? EMBED * HDIM / 4 : HDIM * HDIM / 4;
      for (int idx = tid; idx < nw; idx += NT)
        reinterpret_cast<float4*>(S.Ws)[idx] = reinterpret_cast<const float4*>(Wl[layer])[idx];
      if (layer == 0 && tid >= 1008) {  // zero Ws row 39 (k4 padding)
        reinterpret_cast<float4*>(&S.Ws[EMBED * HDIM])[tid - 1008] = make_float4(0.f, 0.f, 0.f, 0.f);
      }
    }
    if (tid >= 64 && tid < 128) { int j = tid - 64; S.bvec[j] = bl[layer][j]; S.pvec[j] = pl[layer][j]; }
    if (wid == 30) {  // pscale = 1/||p||
      float a = pl[layer][lane], c2 = pl[layer][lane + 32];
      float s2 = a * a + c2 * c2;
#pragma unroll
      for (int o = 16; o; o >>= 1) s2 += __shfl_xor_sync(0xffffffffu, s2, o);
      if (lane == 0) S.red[0] = rsqrtf(s2);
    }
    __syncthreads();

    // ---- GEMM into tmp ----
    if (layer == 0) gemm<10>(cur, tmp, S.Ws, NMAX, tid);
    else            gemm<16>(cur, tmp, S.Ws, n, tid);
    __syncthreads();

    // ---- single-warp scan over hist -> ofs / cursor / dinv; clears hist ----
    if (wid == 0) {
      int c[8];
#pragma unroll
      for (int q = 0; q < 8; ++q) { c[q] = S.hist[lane * 8 + q]; S.hist[lane * 8 + q] = 0; }
      int sum = 0;
#pragma unroll
      for (int q = 0; q < 8; ++q) sum += c[q];
      int incl = sum;
#pragma unroll
      for (int o = 1; o < 32; o <<= 1) {
        int t = __shfl_up_sync(0xffffffffu, incl, o);
        if (lane >= o) incl += t;
      }
      int run = incl - sum;
#pragma unroll
      for (int q = 0; q < 8; ++q) {
        int node = lane * 8 + q;
        S.ofs[node]    = run;
        S.cursor[node] = run;
        S.dinv[node]   = rsqrtf(1.0f + (float)c[q]);
        run += c[q];
      }
      if (lane == 31) S.ofs[NMAX] = run;
    }
    __syncthreads();

    // ---- scatter valid edges (src only), sorted by dst ----
#pragma unroll
    for (int e = tid; e < EDGES; e += NT) {
      unsigned u = S.epack[e];
      if (u >> 16) {
        int d = (u >> 8) & 255;
        int pos = atomicAdd(&S.cursor[d], 1);
        S.esorted[pos] = u & 255u;
      }
    }
    __syncthreads();

    // ---- aggregation (half-warp per node) + relu + fused score -> cur ----
    const float pscale = S.red[0];
    for (int i = hw; i < n; i += NT / 16) {
      const int beg = S.ofs[i], end = S.ofs[i + 1];
      const float di = S.dinv[i];
      unsigned long long a01 = 0ull, a23 = 0ull;
      for (int p = beg; p < end; ++p) {
        const int sN = S.esorted[p];
        unsigned long long cp;
        DUP_F32(cp, S.dinv[sN]);
        const ulonglong2 hv = *reinterpret_cast<const ulonglong2*>(&tmp[sN * XS + hl * 4]);
        FMA_F32X2(a01, cp, hv.x, a01);
        FMA_F32X2(a23, cp, hv.y, a23);
      }
      float av[4];
      asm("mov.b64 {%0, %1}, %2;" : "=f"(av[0]), "=f"(av[1]) : "l"(a01));
      asm("mov.b64 {%0, %1}, %2;" : "=f"(av[2]), "=f"(av[3]) : "l"(a23));
      const float4 hs = *reinterpret_cast<const float4*>(&tmp[i * XS + hl * 4]);
      const float4 bv = *reinterpret_cast<const float4*>(&S.bvec[hl * 4]);
      const float4 pv = *reinterpret_cast<const float4*>(&S.pvec[hl * 4]);
      const float idg = di * di;
      float v0 = fmaxf(av[0] * di + hs.x * idg + bv.x, 0.f);
      float v1 = fmaxf(av[1] * di + hs.y * idg + bv.y, 0.f);
      float v2 = fmaxf(av[2] * di + hs.z * idg + bv.z, 0.f);
      float v3 = fmaxf(av[3] * di + hs.w * idg + bv.w, 0.f);
      float4 vv = {v0, v1, v2, v3};
      *reinterpret_cast<float4*>(&cur[i * XS + hl * 4]) = vv;
      float sc = v0 * pv.x + v1 * pv.y + v2 * pv.z + v3 * pv.w;
#pragma unroll
      for (int o = 8; o; o >>= 1) sc += __shfl_xor_sync(hmask, sc, o);
      if (hl == 0) S.skey64[i] = make_key(tanhf(sc * pscale), i);
    }
    for (int i = n + tid; i < NMAX; i += NT) S.skey64[i] = make_key(-1e30f, i);
    if (tid < NMAX) S.newid[tid] = -1;
    __syncthreads();

    const int kcur = kk3[layer];
    // ---- bitonic sort 256 u64 keys; warps 0-7 only, named barrier ----
    if (tid < 256) {
      {
        unsigned long long k = S.skey64[tid];
#pragma unroll
        for (int ksz = 2; ksz <= 32; ksz <<= 1)
#pragma unroll
          for (int j = ksz >> 1; j > 0; j >>= 1)
            k = ce_shfl(k, j, ((tid & j) == 0) == ((tid & ksz) == 0));
        S.skey64[tid] = k;
      }
      BAR1_256();
#pragma unroll
      for (int ksz = 64; ksz <= 256; ksz <<= 1) {
        for (int j = ksz >> 1; j >= 32; j >>= 1) {
          smem_ce(S.skey64, tid, j, ksz);
          BAR1_256();
        }
        {
          unsigned long long k = S.skey64[tid];
          const bool asc = ((tid & ksz) == 0);
#pragma unroll
          for (int j = 16; j > 0; j >>= 1)
            k = ce_shfl(k, j, ((tid & j) == 0) == asc);
          S.skey64[tid] = k;
        }
        BAR1_256();
      }
      if (tid < kcur) {
        S.newid[(int)(S.skey64[tid] & 0xffffffffull)] = tid;
      }
    }
    __syncthreads();

    // ---- pooled rows -> tmp (scaled, half-warp per rank) ----
    for (int r = hw; r < kcur; r += NT / 16) {
      unsigned long long key = S.skey64[r];
      int old = (int)(key & 0xffffffffull);
      float v = key_score(key);
      float4 h4 = *reinterpret_cast<const float4*>(&cur[old * XS + hl * 4]);
      h4.x *= v; h4.y *= v; h4.z *= v; h4.w *= v;
      *reinterpret_cast<float4*>(&tmp[r * XS + hl * 4]) = h4;
    }
    // ---- fused: edge remap + next-layer histogram ----
    if (layer < 2) {
#pragma unroll
      for (int e = tid; e < EDGES; e += NT) {
        unsigned u = S.epack[e];
        int sN = u & 255, d = (u >> 8) & 255;
        int valid = (int)(u >> 16);
        int ns = S.newid[sN], nd = S.newid[d];
        int nv = (valid && ns >= 0 && nd >= 0) ? 1 : 0;
        if (ns < 0) ns = 0;
        if (nd < 0) nd = 0;
        S.epack[e] = (unsigned)ns | ((unsigned)nd << 8) | ((unsigned)nv << 16);
        if (nv) atomicAdd(&S.hist[nd], 1);
      }
    }
    __syncthreads();

    // ---- readout: warp per column (direct from tmp) ----
    for (int c = wid; c < HDIM; c += NT / 32) {
      float m = -1e30f, sm = 0.f;
      for (int r = lane; r < kcur; r += 32) {
        float v = tmp[r * XS + c];
        m = fmaxf(m, v);
        sm += v;
      }
#pragma unroll
      for (int o = 16; o; o >>= 1) {
        m  = fmaxf(m, __shfl_xor_sync(0xffffffffu, m, o));
        sm += __shfl_xor_sync(0xffffffffu, sm, o);
      }
      if (lane == 0) {
        S.rsum[c]        += m;
        S.rsum[HDIM + c] += sm / (float)kcur;
      }
    }
    float* t = cur; cur = tmp; tmp = t;
    n = kcur;
    __syncthreads();
  }

  // ---- MLP head: 128 -> 64 (256 threads) -> 32 -> 1 ----
  if (tid < 256) {
    int j = tid >> 2, q = tid & 3;
    float a = 0.f;
#pragma unroll 8
    for (int i = q * 32; i < q * 32 + 32; ++i) a += S.rsum[i] * lW1[i * 64 + j];
    a += __shfl_xor_sync(0xffffffffu, a, 1);
    a += __shfl_xor_sync(0xffffffffu, a, 2);
    if (q == 0) S.h1[j] = fmaxf(a + lb1[j], 0.f);
  }
  __syncthreads();
  if (tid < 32) {
    float a = lb2[tid];
#pragma unroll 8
    for (int j = 0; j < 64; ++j) a += S.h1[j] * lW2[j * 32 + tid];
    float h2 = fmaxf(a, 0.f);
    float v = h2 * lW3[tid];
#pragma unroll
    for (int o = 16; o; o >>= 1) v += __shfl_xor_sync(0xffffffffu, v, o);
    if (tid == 0) out[b] = 1.0f / (1.0f + expf(-(v + lb3[0])));
  }
}

extern "C" void kernel_launch(void* const* d_in, const int* in_sizes, int n_in,
                              void* d_out, int out_size) {
  const float* x   = (const float*)d_in[0];
  const int*   ei  = (const int*)d_in[1];
  const float* W1  = (const float*)d_in[2];
  const float* b1  = (const float*)d_in[3];
  const float* p1  = (const float*)d_in[4];
  const float* W2  = (const float*)d_in[5];
  const float* b2  = (const float*)d_in[6];
  const float* p2  = (const float*)d_in[7];
  const float* W3  = (const float*)d_in[8];
  const float* b3  = (const float*)d_in[9];
  const float* p3  = (const float*)d_in[10];
  const float* lW1 = (const float*)d_in[11];
  const float* lb1 = (const float*)d_in[12];
  const float* lW2 = (const float*)d_in[13];
  const float* lb2 = (const float*)d_in[14];
  const float* lW3 = (const float*)d_in[15];
  const float* lb3 = (const float*)d_in[16];
  float* out = (float*)d_out;

  const int B = in_sizes[0] / (NMAX * EMBED);
  const size_t sm = sizeof(Smem);
  cudaFuncSetAttribute(gnn_kernel, cudaFuncAttributeMaxDynamicSharedMemorySize, (int)sm);
  gnn_kernel<<<B, NT, sm>>>(x, ei, W1, b1, p1, W2, b2, p2, W3, b3, p3,
                            lW1, lb1, lW2, lb2, lW3, lb3, out);
}